// round 1
// baseline (speedup 1.0000x reference)
#include <cuda_runtime.h>
#include <math.h>

// Shapes: B=1, H=8, S=512, D=64, P=32.  NTOK = H*S = 4096.
// Factorized algorithm (exact rewrite of reference):
//   f_q[s] = icnn_q(q[s]),  g_k[t] = icnn_k(k[t])
//   phi_q = exp(q @ Wh.T),  phi_k = exp(k @ Wh.T),  u = v @ Wv.T
//   mg = max_t g_k,  m2[p] = max_t u[t,p]           (per head)
//   M[r,p] = sum_t phi_k[t,r] * exp(g_k[t]-mg) * exp(u[t,p]-m2[p])
//   y[s,p] = f_q[s] + mg + m2[p] - log(S) + log(phi_q[s,:] @ M[:,p])

__device__ float g_Wq1T[64*64], g_Wq2T[64*64], g_Wk1T[64*64], g_Wk2T[64*64];
__device__ float g_f[2][4096];          // [0]=f_q, [1]=g_k
__device__ float g_phi[2][4096*32];     // [0]=phi_q, [1]=phi_k
__device__ float g_u[4096*32];
__device__ float g_M[8*32*32];
__device__ float g_mg[8];
__device__ float g_m2[8*32];

__device__ __forceinline__ float softplusf(float x){
    return x > 20.0f ? x : log1pf(expf(x));
}

// --- Kernel 1: softplus + transpose the 4 ICNN weight matrices ---------------
__global__ void prep_kernel(const float* __restrict__ a, const float* __restrict__ b,
                            const float* __restrict__ c, const float* __restrict__ d){
    int i = blockIdx.x * blockDim.x + threadIdx.x;
    if (i < 4096){
        int j = i >> 6, dd = i & 63;     // raw is [j][d] row-major
        int o = dd*64 + j;               // store transposed [d][j]
        g_Wq1T[o] = softplusf(a[i]);
        g_Wq2T[o] = softplusf(b[i]);
        g_Wk1T[o] = softplusf(c[i]);
        g_Wk2T[o] = softplusf(d[i]);
    }
}

// --- Kernel 2/3: per-token ICNN score + phi ---------------------------------
// 128 threads, 16 tokens/block, grid = 256 blocks (4096 tokens).
// which=0 -> q path (g_Wq*, g_f[0], g_phi[0]); which=1 -> k path.
__global__ void __launch_bounds__(128) icnn_phi_kernel(
    const float* __restrict__ x, const float* __restrict__ b1,
    const float* __restrict__ b2, const float* __restrict__ Wh, int which)
{
    __shared__ float sW1[64*64];     // [d][j]
    __shared__ float sW2[64*64];     // [d][j]
    __shared__ float sWh[64*32];     // [d][r]
    __shared__ float sb1[64], sb2[64];
    __shared__ float sx[16][64];
    __shared__ float sz1[8][64];
    __shared__ float spart[2][4][2]; // [grp][tok][warp-half]

    int tid = threadIdx.x;
    const float* W1T = which ? g_Wk1T : g_Wq1T;
    const float* W2T = which ? g_Wk2T : g_Wq2T;
    float* fout   = which ? g_f[1]   : g_f[0];
    float* phiout = which ? g_phi[1] : g_phi[0];

    for (int i = tid; i < 4096; i += 128){ sW1[i] = W1T[i]; sW2[i] = W2T[i]; }
    for (int i = tid; i < 2048; i += 128){ int r = i >> 6, d = i & 63; sWh[d*32 + r] = Wh[i]; }
    if (tid < 64){ sb1[tid] = b1[tid]; sb2[tid] = b2[tid]; }
    int tb = blockIdx.x * 16;
    for (int i = tid; i < 16*64; i += 128) sx[i >> 6][i & 63] = x[tb*64 + i];
    __syncthreads();

    int grp = tid >> 6;          // 0 or 1
    int j   = tid & 63;          // output neuron
    int wh  = (tid >> 5) & 1;    // warp within group

    for (int pass = 0; pass < 2; pass++){
        int lt = pass*8 + grp*4; // first of this group's 4 tokens

        // layer 1: z1[j] for 4 tokens
        float a0 = sb1[j], a1 = a0, a2 = a0, a3 = a0;
        #pragma unroll
        for (int d = 0; d < 64; d++){
            float w = sW1[d*64 + j];
            a0 += sx[lt+0][d]*w; a1 += sx[lt+1][d]*w;
            a2 += sx[lt+2][d]*w; a3 += sx[lt+3][d]*w;
        }
        sz1[grp*4+0][j] = softplusf(a0);
        sz1[grp*4+1][j] = softplusf(a1);
        sz1[grp*4+2][j] = softplusf(a2);
        sz1[grp*4+3][j] = softplusf(a3);
        __syncthreads();

        // layer 2
        float c0 = sb2[j], c1 = c0, c2 = c0, c3 = c0;
        #pragma unroll
        for (int d = 0; d < 64; d++){
            float w = sW2[d*64 + j];
            c0 += sz1[grp*4+0][d]*w; c1 += sz1[grp*4+1][d]*w;
            c2 += sz1[grp*4+2][d]*w; c3 += sz1[grp*4+3][d]*w;
        }
        c0 = softplusf(c0); c1 = softplusf(c1); c2 = softplusf(c2); c3 = softplusf(c3);

        // reduce over j (64 threads = 2 warps per group)
        #pragma unroll
        for (int o = 16; o > 0; o >>= 1){
            c0 += __shfl_xor_sync(0xffffffffu, c0, o);
            c1 += __shfl_xor_sync(0xffffffffu, c1, o);
            c2 += __shfl_xor_sync(0xffffffffu, c2, o);
            c3 += __shfl_xor_sync(0xffffffffu, c3, o);
        }
        if ((tid & 31) == 0){
            spart[grp][0][wh] = c0; spart[grp][1][wh] = c1;
            spart[grp][2][wh] = c2; spart[grp][3][wh] = c3;
        }

        // phi for 4 tokens (threads j<32 handle r=j)
        float p0 = 0.f, p1 = 0.f, p2 = 0.f, p3 = 0.f;
        if (j < 32){
            #pragma unroll
            for (int d = 0; d < 64; d++){
                float w = sWh[d*32 + j];
                p0 += sx[lt+0][d]*w; p1 += sx[lt+1][d]*w;
                p2 += sx[lt+2][d]*w; p3 += sx[lt+3][d]*w;
            }
        }
        __syncthreads();

        if (j < 4) fout[tb + lt + j] = spart[grp][j][0] + spart[grp][j][1];
        if (j < 32){
            phiout[(tb+lt+0)*32 + j] = expf(p0);
            phiout[(tb+lt+1)*32 + j] = expf(p1);
            phiout[(tb+lt+2)*32 + j] = expf(p2);
            phiout[(tb+lt+3)*32 + j] = expf(p3);
        }
        __syncthreads();
    }
}

// --- Kernel 4: u = v @ Wv.T --------------------------------------------------
// 128 threads, 32 tokens/block, grid = 128 blocks.
__global__ void __launch_bounds__(128) u_kernel(const float* __restrict__ v,
                                                const float* __restrict__ Wv){
    __shared__ float sWv[64*32];  // [d][p]
    __shared__ float sx[32][64];
    int tid = threadIdx.x;
    for (int i = tid; i < 2048; i += 128){ int r = i >> 6, d = i & 63; sWv[d*32 + r] = Wv[i]; }
    int tb = blockIdx.x * 32;
    for (int i = tid; i < 32*64; i += 128) sx[i >> 6][i & 63] = v[tb*64 + i];
    __syncthreads();

    int p = tid & 31, g = tid >> 5;  // 4 tokens concurrently
    for (int it = 0; it < 8; it++){
        int t = it*4 + g;
        float acc = 0.f;
        #pragma unroll
        for (int d = 0; d < 64; d++) acc += sx[t][d] * sWv[d*32 + p];
        g_u[(tb + t)*32 + p] = acc;
    }
}

// --- Kernel 5: per-head maxes + M[r,p] contraction --------------------------
__global__ void __launch_bounds__(256) headM_kernel(){
    int h = blockIdx.x, tid = threadIdx.x;
    const float* gk = g_f[1]   + h*512;
    const float* uu = g_u      + h*512*32;
    const float* pk = g_phi[1] + h*512*32;

    __shared__ float red[256];
    __shared__ float s_mg;
    __shared__ float s_m2[32];

    // mg = max_t g_k
    float m = -1e30f;
    for (int t = tid; t < 512; t += 256) m = fmaxf(m, gk[t]);
    red[tid] = m; __syncthreads();
    for (int s = 128; s > 0; s >>= 1){
        if (tid < s) red[tid] = fmaxf(red[tid], red[tid + s]);
        __syncthreads();
    }
    if (tid == 0){ s_mg = red[0]; g_mg[h] = red[0]; }
    __syncthreads();

    // m2[p] = max_t u[t,p]   (8 partial segments per p, then combine)
    {
        int q = tid & 31, sg = tid >> 5;
        float mm = -1e30f;
        for (int t = sg*64; t < sg*64 + 64; t++) mm = fmaxf(mm, uu[t*32 + q]);
        red[tid] = mm; __syncthreads();
        if (tid < 32){
            float vv = red[tid];
            #pragma unroll
            for (int s2 = 1; s2 < 8; s2++) vv = fmaxf(vv, red[s2*32 + tid]);
            s_m2[tid] = vv; g_m2[h*32 + tid] = vv;
        }
        __syncthreads();
    }

    // M[r,p] = sum_t pk[t,r] * exp(gk[t]-mg) * exp(u[t,p]-m2[p])
    __shared__ float seg[64];
    __shared__ float seu[64*32];
    __shared__ float spk[64*32];
    int p = tid & 31, r0 = tid >> 5;     // thread owns rows r0, r0+8, r0+16, r0+24
    float acc0 = 0.f, acc1 = 0.f, acc2 = 0.f, acc3 = 0.f;
    for (int t0 = 0; t0 < 512; t0 += 64){
        for (int i = tid; i < 64; i += 256) seg[i] = expf(gk[t0 + i] - s_mg);
        for (int i = tid; i < 2048; i += 256){
            int t = i >> 5, q = i & 31;
            seu[i] = expf(uu[(t0 + t)*32 + q] - s_m2[q]);
            spk[i] = pk[(t0 + t)*32 + q];
        }
        __syncthreads();
        #pragma unroll 8
        for (int t = 0; t < 64; t++){
            float w = seg[t] * seu[t*32 + p];
            acc0 += spk[t*32 + r0     ] * w;
            acc1 += spk[t*32 + r0 +  8] * w;
            acc2 += spk[t*32 + r0 + 16] * w;
            acc3 += spk[t*32 + r0 + 24] * w;
        }
        __syncthreads();
    }
    g_M[h*1024 + (r0     )*32 + p] = acc0;
    g_M[h*1024 + (r0 +  8)*32 + p] = acc1;
    g_M[h*1024 + (r0 + 16)*32 + p] = acc2;
    g_M[h*1024 + (r0 + 24)*32 + p] = acc3;
}

// --- Kernel 6: y[s,p] = f_q[s] + mg + m2[p] - logS + log(phi_q[s,:] @ M[:,p])
__global__ void __launch_bounds__(256) final_kernel(float* __restrict__ y){
    int h = blockIdx.x, tid = threadIdx.x;
    __shared__ float sM[32*32];
    __shared__ float sm2[32];
    __shared__ float smg;
    for (int i = tid; i < 1024; i += 256) sM[i] = g_M[h*1024 + i];
    if (tid < 32) sm2[tid] = g_m2[h*32 + tid];
    if (tid == 0) smg = g_mg[h];
    __syncthreads();

    const float LOGS = 6.2383246250395077847f;  // log(512)
    int p = tid & 31, s0 = tid >> 5;
    for (int s = s0; s < 512; s += 8){
        const float* pq = g_phi[0] + (h*512 + s)*32;   // broadcast within warp
        float acc = 0.f;
        #pragma unroll
        for (int r = 0; r < 32; r++) acc += pq[r] * sM[r*32 + p];
        y[(h*512 + s)*32 + p] = g_f[0][h*512 + s] + smg + sm2[p] - LOGS + logf(acc);
    }
}

extern "C" void kernel_launch(void* const* d_in, const int* in_sizes, int n_in,
                              void* d_out, int out_size){
    const float* q    = (const float*)d_in[0];
    const float* k    = (const float*)d_in[1];
    const float* v    = (const float*)d_in[2];
    const float* sq1  = (const float*)d_in[3];
    const float* sqb1 = (const float*)d_in[4];
    const float* sq2  = (const float*)d_in[5];
    const float* sqb2 = (const float*)d_in[6];
    const float* sk1  = (const float*)d_in[7];
    const float* skb1 = (const float*)d_in[8];
    const float* sk2  = (const float*)d_in[9];
    const float* skb2 = (const float*)d_in[10];
    const float* Wh   = (const float*)d_in[11];
    const float* Wv   = (const float*)d_in[12];
    float* y = (float*)d_out;

    prep_kernel<<<16, 256>>>(sq1, sq2, sk1, sk2);
    icnn_phi_kernel<<<256, 128>>>(q, sqb1, sqb2, Wh, 0);
    icnn_phi_kernel<<<256, 128>>>(k, skb1, skb2, Wh, 1);
    u_kernel<<<128, 128>>>(v, Wv);
    headM_kernel<<<8, 256>>>();
    final_kernel<<<8, 256>>>(y);
}

// round 2
// speedup vs baseline: 4.0800x; 4.0800x over previous
#include <cuda_runtime.h>
#include <math.h>

// Shapes: B=1, H=8, S=512, D=64, P=32.  NTOK = 4096.
// Factorized exact rewrite:
//   f_q[s] = icnn_q(q[s]),  g_k[t] = icnn_k(k[t])
//   phi_q = exp(q @ Wh.T),  phi_k = exp(k @ Wh.T),  u = v @ Wv.T
//   mg = max_t g_k,  m2[p] = max_t u[t,p]           (per head)
//   M[r,p] = sum_t phi_k[t,r] * exp(g_k[t]-mg) * exp(u[t,p]-m2[p])
//   y[s,p] = f_q[s] + mg + m2[p] - log(S) + log(phi_q[s,:] @ M[:,p])
//
// Single persistent kernel, grid=144 blocks (<=148 SMs -> all resident),
// 2 grid barriers between 3 phases.

#define G 144
#define T 512

__device__ float g_f[2][4096];          // [0]=f_q, [1]=g_k
__device__ float g_phi[2][4096*32];     // [0]=phi_q, [1]=phi_k
__device__ float g_u[4096*32];
__device__ float g_Mpart[64][1024];     // [h*8+c][r*32+p]
__device__ unsigned g_mg_ord[8];        // order-encoded maxes (0 == -inf sentinel)
__device__ unsigned g_m2_ord[8*32];
__device__ unsigned long long g_bar;    // monotonic ticket barrier

__device__ __forceinline__ float softplusf(float x){
    return x > 20.0f ? x : log1pf(expf(x));
}
__device__ __forceinline__ unsigned ordf(float f){
    unsigned u = __float_as_uint(f);
    return (u & 0x80000000u) ? ~u : (u | 0x80000000u);
}
__device__ __forceinline__ float deco(unsigned k){
    return __uint_as_float((k & 0x80000000u) ? (k ^ 0x80000000u) : ~k);
}

__device__ __forceinline__ void gridbar(){
    __syncthreads();
    if (threadIdx.x == 0){
        __threadfence();
        unsigned long long t = atomicAdd(&g_bar, 1ULL);
        unsigned long long target = (t / G + 1ULL) * G;
        while (*((volatile unsigned long long*)&g_bar) < target) { }
        __threadfence();
    }
    __syncthreads();
}

// dynamic smem: max usage 19200 floats (icnn role) = 76800 bytes
#define SMEM_FLOATS 19200

__global__ void __launch_bounds__(T, 1) fused_kernel(
    const float* __restrict__ q,  const float* __restrict__ k,  const float* __restrict__ v,
    const float* __restrict__ sq1, const float* __restrict__ sqb1,
    const float* __restrict__ sq2, const float* __restrict__ sqb2,
    const float* __restrict__ sk1, const float* __restrict__ skb1,
    const float* __restrict__ sk2, const float* __restrict__ skb2,
    const float* __restrict__ Wh, const float* __restrict__ Wv,
    float* __restrict__ y)
{
    extern __shared__ float S[];
    const int tid = threadIdx.x;
    const int bid = blockIdx.x;

    // ============================ PHASE 1 ============================
    if (bid < 128){
        // ---- ICNN + phi for q (bid<64) or k (bid>=64) ----
        const int which = (bid >= 64);
        const float* x    = which ? k   : q;
        const float* raw1 = which ? sk1 : sq1;
        const float* raw2 = which ? sk2 : sq2;
        const float* b1   = which ? skb1: sqb1;
        const float* b2   = which ? skb2: sqb2;
        const int tb = (which ? bid - 64 : bid) * 64;   // token base
        const int h  = tb >> 9;

        float* sW1  = S;                    // [64][68]
        float* sW2  = sW1 + 64*68;          // [64][68]
        float* sWhT = sW2 + 64*68;          // [d][r] 64x32
        float* sx   = sWhT + 64*32;         // [64][64]
        float* sz1  = sx + 64*64;           // [64][64]
        float* sb1  = sz1 + 64*64;          // 64
        float* sb2  = sb1 + 64;             // 64
        float* sred = sb2 + 64;             // 128

        for (int i = tid; i < 4096; i += T){
            int j = i >> 6, d = i & 63;
            sW1[j*68 + d] = softplusf(raw1[i]);
            sW2[j*68 + d] = softplusf(raw2[i]);
        }
        for (int i = tid; i < 2048; i += T){
            int r = i >> 6, d = i & 63;
            sWhT[d*32 + r] = Wh[i];
        }
        for (int i = tid; i < 4096; i += T) sx[i] = x[tb*64 + i];
        if (tid < 64){ sb1[tid] = b1[tid]; sb2[tid] = b2[tid]; }
        __syncthreads();

        const int grp = tid >> 6;        // 0..7, 8 tokens each
        const int j   = tid & 63;
        const int t0  = grp * 8;

        // layer 1
        float acc[8];
        {
            float b = sb1[j];
            #pragma unroll
            for (int i = 0; i < 8; i++) acc[i] = b;
            #pragma unroll
            for (int d = 0; d < 64; d += 4){
                float4 w = *(const float4*)&sW1[j*68 + d];
                #pragma unroll
                for (int i = 0; i < 8; i++){
                    float4 xv = *(const float4*)&sx[(t0+i)*64 + d];
                    acc[i] += xv.x*w.x + xv.y*w.y + xv.z*w.z + xv.w*w.w;
                }
            }
            #pragma unroll
            for (int i = 0; i < 8; i++) sz1[(t0+i)*64 + j] = softplusf(acc[i]);
        }
        __syncthreads();

        // layer 2 + reduce over j
        {
            float b = sb2[j];
            #pragma unroll
            for (int i = 0; i < 8; i++) acc[i] = b;
            #pragma unroll
            for (int d = 0; d < 64; d += 4){
                float4 w = *(const float4*)&sW2[j*68 + d];
                #pragma unroll
                for (int i = 0; i < 8; i++){
                    float4 zv = *(const float4*)&sz1[(t0+i)*64 + d];
                    acc[i] += zv.x*w.x + zv.y*w.y + zv.z*w.z + zv.w*w.w;
                }
            }
            #pragma unroll
            for (int i = 0; i < 8; i++){
                float c = softplusf(acc[i]);
                #pragma unroll
                for (int o = 16; o > 0; o >>= 1)
                    c += __shfl_xor_sync(0xffffffffu, c, o);
                acc[i] = c;
            }
            if ((tid & 31) == 0){
                int w = tid >> 5;   // warp 0..15
                #pragma unroll
                for (int i = 0; i < 8; i++) sred[w*8 + i] = acc[i];
            }
        }
        __syncthreads();

        if (tid < 64){
            int t = tid, g2 = t >> 3, i2 = t & 7;
            float f = sred[(g2*2    )*8 + i2] + sred[(g2*2 + 1)*8 + i2];
            g_f[which][tb + t] = f;
            if (which){
                float m = f;
                #pragma unroll
                for (int o = 16; o > 0; o >>= 1)
                    m = fmaxf(m, __shfl_xor_sync(0xffffffffu, m, o));
                if ((tid & 31) == 0) atomicMax(&g_mg_ord[h], ordf(m));
            }
        }

        // phi: 64 tokens x 32 r
        for (int pair = tid; pair < 2048; pair += T){
            int t = pair >> 5, r = pair & 31;
            float a = 0.f;
            #pragma unroll
            for (int d = 0; d < 64; d += 4){
                float4 xv = *(const float4*)&sx[t*64 + d];
                a += xv.x*sWhT[(d  )*32 + r] + xv.y*sWhT[(d+1)*32 + r]
                   + xv.z*sWhT[(d+2)*32 + r] + xv.w*sWhT[(d+3)*32 + r];
            }
            g_phi[which][(tb + t)*32 + r] = expf(a);
        }
    } else {
        // ---- u = v @ Wv.T, blocks 128..143, 256 tokens each ----
        const int ub = bid - 128;
        const int tb = ub * 256;
        const int h  = tb >> 9;
        float* sWvT = S;               // [d][p] 64x32
        float* sv   = S + 2048;        // 256x64
        float* sred = S + 2048 + 16384;// 512

        for (int i = tid; i < 2048; i += T){
            int r = i >> 6, d = i & 63;
            sWvT[d*32 + r] = Wv[i];
        }
        for (int i = tid; i < 16384; i += T) sv[i] = v[tb*64 + i];
        __syncthreads();

        const int p = tid & 31, tr = tid >> 5;
        float mx = -1e30f;
        for (int t = tr; t < 256; t += 16){
            float a = 0.f;
            #pragma unroll
            for (int d = 0; d < 64; d += 4){
                float4 xv = *(const float4*)&sv[t*64 + d];
                a += xv.x*sWvT[(d  )*32 + p] + xv.y*sWvT[(d+1)*32 + p]
                   + xv.z*sWvT[(d+2)*32 + p] + xv.w*sWvT[(d+3)*32 + p];
            }
            g_u[(tb + t)*32 + p] = a;
            mx = fmaxf(mx, a);
        }
        sred[tr*32 + p] = mx;
        __syncthreads();
        if (tid < 32){
            float m = sred[tid];
            #pragma unroll
            for (int rr = 1; rr < 16; rr++) m = fmaxf(m, sred[rr*32 + tid]);
            atomicMax(&g_m2_ord[h*32 + tid], ordf(m));
        }
    }

    gridbar();

    // ============================ PHASE 2 ============================
    // partial M per (head, 64-token chunk): 64 blocks
    if (bid < 64){
        const int h = bid >> 3, c = bid & 7;
        const int gtb = h*512 + c*64;
        float* seg = S;          // 64
        float* sm2 = S + 64;     // 32
        float* sw  = S + 96;     // 64x32
        float* spk = S + 96 + 2048; // 64x32

        float mg = deco(__ldcg(&g_mg_ord[h]));
        if (tid < 32) sm2[tid] = deco(__ldcg(&g_m2_ord[h*32 + tid]));
        if (tid >= 64 && tid < 128) seg[tid - 64] = expf(__ldcg(&g_f[1][gtb + tid - 64]) - mg);
        __syncthreads();

        for (int i = tid; i < 2048; i += T){
            int t = i >> 5, p = i & 31;
            sw[i]  = seg[t] * expf(__ldcg(&g_u[(gtb + t)*32 + p]) - sm2[p]);
            spk[i] = __ldcg(&g_phi[1][(gtb + t)*32 + p]);
        }
        __syncthreads();

        for (int o = tid; o < 1024; o += T){
            int r = o >> 5, p = o & 31;
            float a = 0.f;
            #pragma unroll
            for (int t = 0; t < 64; t++) a += spk[t*32 + r] * sw[t*32 + p];
            g_Mpart[bid][o] = a;
        }
    }

    gridbar();

    // ============================ PHASE 3 ============================
    // y for (head, 32-token s-chunk): 128 blocks
    if (bid < 128){
        const int h = bid >> 4, sc = bid & 15;
        const int s0 = h*512 + sc*32;
        float* sM  = S;          // 32x32
        float* spq = S + 1024;   // 32x32
        float* sm2 = S + 2048;   // 32
        float* sf  = S + 2080;   // 32

        for (int o = tid; o < 1024; o += T){
            float a = 0.f;
            #pragma unroll
            for (int c = 0; c < 8; c++) a += __ldcg(&g_Mpart[h*8 + c][o]);
            sM[o] = a;
        }
        for (int i = tid; i < 1024; i += T) spq[i] = __ldcg(&g_phi[0][s0*32 + i]);
        if (tid < 32){
            sm2[tid] = deco(__ldcg(&g_m2_ord[h*32 + tid]));
            sf[tid]  = __ldcg(&g_f[0][s0 + tid]);
        }
        float mg = deco(__ldcg(&g_mg_ord[h]));
        __syncthreads();

        const float LOGS = 6.2383246250395077847f; // log(512)
        for (int o = tid; o < 1024; o += T){
            int s = o >> 5, p = o & 31;
            float a = 0.f;
            #pragma unroll
            for (int r = 0; r < 32; r++) a += spq[s*32 + r] * sM[r*32 + p];
            y[(s0 + s)*32 + p] = sf[s] + mg + sm2[p] - LOGS + logf(a);
        }
    }
}

extern "C" void kernel_launch(void* const* d_in, const int* in_sizes, int n_in,
                              void* d_out, int out_size){
    const float* q    = (const float*)d_in[0];
    const float* k    = (const float*)d_in[1];
    const float* v    = (const float*)d_in[2];
    const float* sq1  = (const float*)d_in[3];
    const float* sqb1 = (const float*)d_in[4];
    const float* sq2  = (const float*)d_in[5];
    const float* sqb2 = (const float*)d_in[6];
    const float* sk1  = (const float*)d_in[7];
    const float* skb1 = (const float*)d_in[8];
    const float* sk2  = (const float*)d_in[9];
    const float* skb2 = (const float*)d_in[10];
    const float* Wh   = (const float*)d_in[11];
    const float* Wv   = (const float*)d_in[12];
    float* y = (float*)d_out;

    static_assert(SMEM_FLOATS * sizeof(float) == 76800, "smem size");
    cudaFuncSetAttribute(fused_kernel, cudaFuncAttributeMaxDynamicSharedMemorySize,
                         SMEM_FLOATS * (int)sizeof(float));
    fused_kernel<<<G, T, SMEM_FLOATS * sizeof(float)>>>(
        q, k, v, sq1, sqb1, sq2, sqb2, sk1, skb1, sk2, skb2, Wh, Wv, y);
}

// round 7
// speedup vs baseline: 4.3880x; 1.0755x over previous
#include <cuda_runtime.h>
#include <math.h>

// EXACT Round-2 structure (known passing @29.2us). Only changes:
//  - expf/logf/log1pf -> __expf/__logf intrinsics (arithmetic only)
//  - phase-3 spq global load scalarized (was float4 __ldcg)

#define G 144
#define T 512

__device__ float g_f[2][4096];          // [0]=f_q, [1]=g_k
__device__ float g_phi[2][4096*32];     // [0]=phi_q, [1]=phi_k
__device__ float g_u[4096*32];
__device__ float g_Mpart[64][1024];     // [h*8+c][r*32+p]
__device__ unsigned g_mg_ord[8];        // order-encoded maxes (0 == -inf sentinel)
__device__ unsigned g_m2_ord[8*32];
__device__ unsigned long long g_bar;    // monotonic ticket barrier

__device__ __forceinline__ float softplusf(float x){
    return x > 20.0f ? x : __logf(1.0f + __expf(x));
}
__device__ __forceinline__ unsigned ordf(float f){
    unsigned u = __float_as_uint(f);
    return (u & 0x80000000u) ? ~u : (u | 0x80000000u);
}
__device__ __forceinline__ float deco(unsigned k){
    return __uint_as_float((k & 0x80000000u) ? (k ^ 0x80000000u) : ~k);
}

__device__ __forceinline__ void gridbar(){
    __syncthreads();
    if (threadIdx.x == 0){
        __threadfence();
        unsigned long long t = atomicAdd(&g_bar, 1ULL);
        unsigned long long target = (t / G + 1ULL) * G;
        while (*((volatile unsigned long long*)&g_bar) < target) { }
        __threadfence();
    }
    __syncthreads();
}

// dynamic smem: max usage 19200 floats (icnn role) = 76800 bytes
#define SMEM_FLOATS 19200

__global__ void __launch_bounds__(T, 1) fused_kernel(
    const float* __restrict__ q,  const float* __restrict__ k,  const float* __restrict__ v,
    const float* __restrict__ sq1, const float* __restrict__ sqb1,
    const float* __restrict__ sq2, const float* __restrict__ sqb2,
    const float* __restrict__ sk1, const float* __restrict__ skb1,
    const float* __restrict__ sk2, const float* __restrict__ skb2,
    const float* __restrict__ Wh, const float* __restrict__ Wv,
    float* __restrict__ y)
{
    extern __shared__ float S[];
    const int tid = threadIdx.x;
    const int bid = blockIdx.x;

    // ============================ PHASE 1 ============================
    if (bid < 128){
        // ---- ICNN + phi for q (bid<64) or k (bid>=64) ----
        const int which = (bid >= 64);
        const float* x    = which ? k   : q;
        const float* raw1 = which ? sk1 : sq1;
        const float* raw2 = which ? sk2 : sq2;
        const float* b1   = which ? skb1: sqb1;
        const float* b2   = which ? skb2: sqb2;
        const int tb = (which ? bid - 64 : bid) * 64;   // token base
        const int h  = tb >> 9;

        float* sW1  = S;                    // [64][68]
        float* sW2  = sW1 + 64*68;          // [64][68]
        float* sWhT = sW2 + 64*68;          // [d][r] 64x32
        float* sx   = sWhT + 64*32;         // [64][64]
        float* sz1  = sx + 64*64;           // [64][64]
        float* sb1  = sz1 + 64*64;          // 64
        float* sb2  = sb1 + 64;             // 64
        float* sred = sb2 + 64;             // 128

        for (int i = tid; i < 4096; i += T){
            int j = i >> 6, d = i & 63;
            sW1[j*68 + d] = softplusf(raw1[i]);
            sW2[j*68 + d] = softplusf(raw2[i]);
        }
        for (int i = tid; i < 2048; i += T){
            int r = i >> 6, d = i & 63;
            sWhT[d*32 + r] = Wh[i];
        }
        for (int i = tid; i < 4096; i += T) sx[i] = x[tb*64 + i];
        if (tid < 64){ sb1[tid] = b1[tid]; sb2[tid] = b2[tid]; }
        __syncthreads();

        const int grp = tid >> 6;        // 0..7, 8 tokens each
        const int j   = tid & 63;
        const int t0  = grp * 8;

        // layer 1
        float acc[8];
        {
            float b = sb1[j];
            #pragma unroll
            for (int i = 0; i < 8; i++) acc[i] = b;
            #pragma unroll
            for (int d = 0; d < 64; d += 4){
                float4 w = *(const float4*)&sW1[j*68 + d];
                #pragma unroll
                for (int i = 0; i < 8; i++){
                    float4 xv = *(const float4*)&sx[(t0+i)*64 + d];
                    acc[i] += xv.x*w.x + xv.y*w.y + xv.z*w.z + xv.w*w.w;
                }
            }
            #pragma unroll
            for (int i = 0; i < 8; i++) sz1[(t0+i)*64 + j] = softplusf(acc[i]);
        }
        __syncthreads();

        // layer 2 + reduce over j
        {
            float b = sb2[j];
            #pragma unroll
            for (int i = 0; i < 8; i++) acc[i] = b;
            #pragma unroll
            for (int d = 0; d < 64; d += 4){
                float4 w = *(const float4*)&sW2[j*68 + d];
                #pragma unroll
                for (int i = 0; i < 8; i++){
                    float4 zv = *(const float4*)&sz1[(t0+i)*64 + d];
                    acc[i] += zv.x*w.x + zv.y*w.y + zv.z*w.z + zv.w*w.w;
                }
            }
            #pragma unroll
            for (int i = 0; i < 8; i++){
                float c = softplusf(acc[i]);
                #pragma unroll
                for (int o = 16; o > 0; o >>= 1)
                    c += __shfl_xor_sync(0xffffffffu, c, o);
                acc[i] = c;
            }
            if ((tid & 31) == 0){
                int w = tid >> 5;   // warp 0..15
                #pragma unroll
                for (int i = 0; i < 8; i++) sred[w*8 + i] = acc[i];
            }
        }
        __syncthreads();

        if (tid < 64){
            int t = tid, g2 = t >> 3, i2 = t & 7;
            float f = sred[(g2*2    )*8 + i2] + sred[(g2*2 + 1)*8 + i2];
            g_f[which][tb + t] = f;
            if (which){
                float m = f;
                #pragma unroll
                for (int o = 16; o > 0; o >>= 1)
                    m = fmaxf(m, __shfl_xor_sync(0xffffffffu, m, o));
                if ((tid & 31) == 0) atomicMax(&g_mg_ord[h], ordf(m));
            }
        }

        // phi: 64 tokens x 32 r
        for (int pair = tid; pair < 2048; pair += T){
            int t = pair >> 5, r = pair & 31;
            float a = 0.f;
            #pragma unroll
            for (int d = 0; d < 64; d += 4){
                float4 xv = *(const float4*)&sx[t*64 + d];
                a += xv.x*sWhT[(d  )*32 + r] + xv.y*sWhT[(d+1)*32 + r]
                   + xv.z*sWhT[(d+2)*32 + r] + xv.w*sWhT[(d+3)*32 + r];
            }
            g_phi[which][(tb + t)*32 + r] = __expf(a);
        }
    } else {
        // ---- u = v @ Wv.T, blocks 128..143, 256 tokens each ----
        const int ub = bid - 128;
        const int tb = ub * 256;
        const int h  = tb >> 9;
        float* sWvT = S;               // [d][p] 64x32
        float* sv   = S + 2048;        // 256x64
        float* sred = S + 2048 + 16384;// 512

        for (int i = tid; i < 2048; i += T){
            int r = i >> 6, d = i & 63;
            sWvT[d*32 + r] = Wv[i];
        }
        for (int i = tid; i < 16384; i += T) sv[i] = v[tb*64 + i];
        __syncthreads();

        const int p = tid & 31, tr = tid >> 5;
        float mx = -1e30f;
        for (int t = tr; t < 256; t += 16){
            float a = 0.f;
            #pragma unroll
            for (int d = 0; d < 64; d += 4){
                float4 xv = *(const float4*)&sv[t*64 + d];
                a += xv.x*sWvT[(d  )*32 + p] + xv.y*sWvT[(d+1)*32 + p]
                   + xv.z*sWvT[(d+2)*32 + p] + xv.w*sWvT[(d+3)*32 + p];
            }
            g_u[(tb + t)*32 + p] = a;
            mx = fmaxf(mx, a);
        }
        sred[tr*32 + p] = mx;
        __syncthreads();
        if (tid < 32){
            float m = sred[tid];
            #pragma unroll
            for (int rr = 1; rr < 16; rr++) m = fmaxf(m, sred[rr*32 + tid]);
            atomicMax(&g_m2_ord[h*32 + tid], ordf(m));
        }
    }

    gridbar();

    // ============================ PHASE 2 ============================
    // partial M per (head, 64-token chunk): 64 blocks
    if (bid < 64){
        const int h = bid >> 3, c = bid & 7;
        const int gtb = h*512 + c*64;
        float* seg = S;          // 64
        float* sm2 = S + 64;     // 32
        float* sw  = S + 96;     // 64x32
        float* spk = S + 96 + 2048; // 64x32

        float mg = deco(__ldcg(&g_mg_ord[h]));
        if (tid < 32) sm2[tid] = deco(__ldcg(&g_m2_ord[h*32 + tid]));
        if (tid >= 64 && tid < 128) seg[tid - 64] = __expf(__ldcg(&g_f[1][gtb + tid - 64]) - mg);
        __syncthreads();

        for (int i = tid; i < 2048; i += T){
            int t = i >> 5, p = i & 31;
            sw[i]  = seg[t] * __expf(__ldcg(&g_u[(gtb + t)*32 + p]) - sm2[p]);
            spk[i] = __ldcg(&g_phi[1][(gtb + t)*32 + p]);
        }
        __syncthreads();

        for (int o = tid; o < 1024; o += T){
            int r = o >> 5, p = o & 31;
            float a = 0.f;
            #pragma unroll
            for (int t = 0; t < 64; t++) a += spk[t*32 + r] * sw[t*32 + p];
            g_Mpart[bid][o] = a;
        }
    }

    gridbar();

    // ============================ PHASE 3 ============================
    // y for (head, 32-token s-chunk): 128 blocks
    if (bid < 128){
        const int h = bid >> 4, sc = bid & 15;
        const int s0 = h*512 + sc*32;
        float* sM  = S;          // 32x32
        float* spq = S + 1024;   // 32x32
        float* sm2 = S + 2048;   // 32
        float* sf  = S + 2080;   // 32

        for (int o = tid; o < 1024; o += T){
            float a = 0.f;
            #pragma unroll
            for (int c = 0; c < 8; c++) a += __ldcg(&g_Mpart[h*8 + c][o]);
            sM[o] = a;
        }
        for (int i = tid; i < 1024; i += T) spq[i] = __ldcg(&g_phi[0][s0*32 + i]);
        if (tid < 32){
            sm2[tid] = deco(__ldcg(&g_m2_ord[h*32 + tid]));
            sf[tid]  = __ldcg(&g_f[0][s0 + tid]);
        }
        float mg = deco(__ldcg(&g_mg_ord[h]));
        __syncthreads();

        const float LOGS = 6.2383246250395077847f; // log(512)
        for (int o = tid; o < 1024; o += T){
            int s = o >> 5, p = o & 31;
            float a = 0.f;
            #pragma unroll
            for (int r = 0; r < 32; r++) a += spq[s*32 + r] * sM[r*32 + p];
            y[(s0 + s)*32 + p] = sf[s] + mg + sm2[p] - LOGS + __logf(a);
        }
    }
}

extern "C" void kernel_launch(void* const* d_in, const int* in_sizes, int n_in,
                              void* d_out, int out_size){
    const float* q    = (const float*)d_in[0];
    const float* k    = (const float*)d_in[1];
    const float* v    = (const float*)d_in[2];
    const float* sq1  = (const float*)d_in[3];
    const float* sqb1 = (const float*)d_in[4];
    const float* sq2  = (const float*)d_in[5];
    const float* sqb2 = (const float*)d_in[6];
    const float* sk1  = (const float*)d_in[7];
    const float* skb1 = (const float*)d_in[8];
    const float* sk2  = (const float*)d_in[9];
    const float* skb2 = (const float*)d_in[10];
    const float* Wh   = (const float*)d_in[11];
    const float* Wv   = (const float*)d_in[12];
    float* y = (float*)d_out;

    cudaFuncSetAttribute(fused_kernel, cudaFuncAttributeMaxDynamicSharedMemorySize,
                         SMEM_FLOATS * (int)sizeof(float));
    fused_kernel<<<G, T, SMEM_FLOATS * sizeof(float)>>>(
        q, k, v, sq1, sqb1, sq2, sqb2, sk1, skb1, sk2, skb2, Wh, Wv, y);
}